// round 16
// baseline (speedup 1.0000x reference)
#include <cuda_runtime.h>
#include <cuda_fp16.h>
#include <cstdint>

#define BB 8
#define SS 2048
#define DD 512

// ---------------- device-global scratch (allocation-free) -------------------
__device__ __align__(16) __half g_x16 [(size_t)BB * SS * DD];  // X plain fp16
__device__ __align__(16) __half g_x16c[(size_t)BB * SS * DD];  // compacted X
__device__ __align__(16) __half g_w16 [3 * DD * DD];           // W plain fp16
__device__ __align__(16) __half g_q16 [(size_t)BB * SS * DD];  // Q plain fp16 (unscaled)
__device__ __align__(16) __half g_k16 [(size_t)BB * SS * DD];  // K plain fp16, compacted
__device__ __align__(16) __half g_vt16[(size_t)BB * DD * SS];  // V^T plain fp16 [b][d][slot]
__device__ __align__(16) __half g_p16 [(size_t)BB * SS * SS];  // logits -> probs (in place)
__device__ int g_slot[BB * SS];
__device__ int g_nvalid[BB];
__device__ int g_npad[BB];

// ---------------- PTX helpers ----------------------------------------------
static __device__ __forceinline__ uint32_t su32(const void* p) {
    return (uint32_t)__cvta_generic_to_shared(p);
}
__device__ __forceinline__ void cp16(uint32_t dst, const void* src) {
    asm volatile("cp.async.cg.shared.global [%0], [%1], 16;" :: "r"(dst), "l"(src));
}
__device__ __forceinline__ void cp_commit() {
    asm volatile("cp.async.commit_group;" ::: "memory");
}
template <int N>
__device__ __forceinline__ void cp_wait() {
    asm volatile("cp.async.wait_group %0;" :: "n"(N) : "memory");
}
__device__ __forceinline__ void ldm_x4(uint32_t addr, uint32_t r[4]) {
    asm volatile("ldmatrix.sync.aligned.m8n8.x4.shared.b16 {%0,%1,%2,%3}, [%4];"
                 : "=r"(r[0]), "=r"(r[1]), "=r"(r[2]), "=r"(r[3]) : "r"(addr));
}
__device__ __forceinline__ void mma_f16(float c[4], const uint32_t a[4], const uint32_t b[2]) {
    asm volatile(
        "mma.sync.aligned.m16n8k16.row.col.f32.f16.f16.f32 "
        "{%0,%1,%2,%3}, {%4,%5,%6,%7}, {%8,%9}, {%0,%1,%2,%3};"
        : "+f"(c[0]), "+f"(c[1]), "+f"(c[2]), "+f"(c[3])
        : "r"(a[0]), "r"(a[1]), "r"(a[2]), "r"(a[3]), "r"(b[0]), "r"(b[1]));
}
__device__ __forceinline__ uint32_t pack_h2(float a, float b) {
    __half2 t(__float2half(a), __float2half(b));
    return *reinterpret_cast<uint32_t*>(&t);
}

// ---------------- single-pass fp16 GEMM, CTA 128x128, 4 warps of 64x64 -------
// C(128x128) = A[128,K] * B[128,K]^T. 128 threads: warps 2(m) x 2(n).
// Stage = A(128x16) + B(128x16) fp16 at 48B pitch.
#define PITCH 48
#define TILE_B 6144            // 128 * 48
#define STAGE_B 12288          // 2 * TILE_B
#define NSTG 4
#define SMEM_BYTES (NSTG * STAGE_B)   // 49152

__device__ __forceinline__ void gemm_1p(const __half* __restrict__ Ag,
                                        const __half* __restrict__ Bg,
                                        int K, int ldA, int ldB,
                                        int m0, int n0,
                                        char* smem, float acc[4][8][4]) {
    const int tid  = threadIdx.x;
    const int lane = tid & 31;
    const int w    = tid >> 5;     // 0..3
    const int wm   = w & 1;        // 2 m-positions x 64 rows
    const int wn   = w >> 1;       // 2 n-positions x 64 cols
    const uint32_t sbase = su32(smem);

#pragma unroll
    for (int mi = 0; mi < 4; mi++)
#pragma unroll
        for (int nj = 0; nj < 8; nj++)
#pragma unroll
            for (int e = 0; e < 4; e++) acc[mi][nj][e] = 0.0f;

    const int NK = K >> 4;

    const uint32_t offA = (uint32_t)(wm * 64 + (lane & 15)) * PITCH + (lane >> 4) * 16;
    const uint32_t offB = (uint32_t)(wn * 64 + (lane & 7) + ((lane >> 4) << 3)) * PITCH
                        + (((lane >> 3) & 1) << 4);

    // 128 threads: each owns one row (tid) and copies both 16B chunks of A & B.
#define ISSUE1(kidx)                                                              \
    do {                                                                          \
        const int k0 = (kidx) << 4;                                               \
        uint32_t st = sbase + ((kidx) & (NSTG - 1)) * STAGE_B;                    \
        size_t ga = (size_t)(m0 + tid) * ldA + k0;                                \
        size_t gb = (size_t)(n0 + tid) * ldB + k0;                                \
        uint32_t da = st + tid * PITCH;                                           \
        cp16(da,               Ag + ga);                                          \
        cp16(da + 16,          Ag + ga + 8);                                      \
        cp16(da + TILE_B,      Bg + gb);                                          \
        cp16(da + TILE_B + 16, Bg + gb + 8);                                      \
        cp_commit();                                                              \
    } while (0)

    ISSUE1(0); ISSUE1(1); ISSUE1(2);

    for (int k = 0; k < NK; k++) {
        cp_wait<2>();
        __syncthreads();

        const uint32_t st = sbase + (k & (NSTG - 1)) * STAGE_B;
        uint32_t ah[4][4];
#pragma unroll
        for (int mi = 0; mi < 4; mi++)
            ldm_x4(st + offA + (uint32_t)(mi * 16 * PITCH), ah[mi]);
        uint32_t bh[8][2];
#pragma unroll
        for (int nj4 = 0; nj4 < 4; nj4++) {
            uint32_t t[4];
            ldm_x4(st + TILE_B + offB + (uint32_t)(nj4 * 16 * PITCH), t);
            bh[2 * nj4][0] = t[0]; bh[2 * nj4][1] = t[1];
            bh[2 * nj4 + 1][0] = t[2]; bh[2 * nj4 + 1][1] = t[3];
        }

#pragma unroll
        for (int mi = 0; mi < 4; mi++)
#pragma unroll
            for (int nj = 0; nj < 8; nj++)
                mma_f16(acc[mi][nj], ah[mi], bh[nj]);

        if (k + 3 < NK) ISSUE1(k + 3);
        else            cp_commit();
    }
#undef ISSUE1
}

// ---------------- kernels ----------------------------------------------------
#define NX4 ((BB * SS * DD) / 4)
#define NW4 ((DD * DD) / 4)
__global__ void __launch_bounds__(256)
convert_all(const float* __restrict__ X, const float* __restrict__ Wq,
            const float* __restrict__ Wk, const float* __restrict__ Wv) {
    int i = blockIdx.x * blockDim.x + threadIdx.x;
    const float* src;
    __half* dst;
    int j;
    if (i < NX4) {
        src = X; dst = g_x16; j = i;
    } else {
        int i2 = i - NX4;
        int wsel = i2 / NW4;
        j = i2 - wsel * NW4;
        if (wsel >= 3) return;
        src = (wsel == 0) ? Wq : ((wsel == 1) ? Wk : Wv);
        dst = g_w16 + (size_t)wsel * DD * DD;
    }
    float4 v = reinterpret_cast<const float4*>(src)[j];
    reinterpret_cast<uint2*>(dst)[j] = make_uint2(pack_h2(v.x, v.y), pack_h2(v.z, v.w));
}

__global__ void __launch_bounds__(256)
build_index(const int* __restrict__ mask) {
    const int b = blockIdx.x;
    const int t = threadIdx.x;
    const int* m = mask + b * SS;
    const int base = t * 8;
    int loc[8], cnt = 0;
#pragma unroll
    for (int i = 0; i < 8; i++) { loc[i] = (m[base + i] != 0); cnt += loc[i]; }
    const int lane = t & 31, w = t >> 5;
    int v = cnt;
#pragma unroll
    for (int o = 1; o < 32; o <<= 1) {
        int u = __shfl_up_sync(0xffffffffu, v, o);
        if (lane >= o) v += u;
    }
    __shared__ int ws[8];
    if (lane == 31) ws[w] = v;
    __syncthreads();
    int wo = 0;
#pragma unroll
    for (int i = 0; i < 8; i++) if (i < w) wo += ws[i];
    int excl = wo + v - cnt;
#pragma unroll
    for (int i = 0; i < 8; i++) {
        g_slot[b * SS + base + i] = loc[i] ? excl : -1;
        excl += loc[i];
    }
    if (t == 255) {
        int tot = wo + v;
        g_nvalid[b] = tot;
        g_npad[b]   = (tot + 127) & ~127;
    }
}

__global__ void __launch_bounds__(256)
gather_x() {
    const int r = blockIdx.x * 8 + (threadIdx.x >> 5);
    const int lane = threadIdx.x & 31;
    const int slot = g_slot[r];
    if (slot < 0) return;
    const int b = r >> 11;
    const uint4* s = reinterpret_cast<const uint4*>(g_x16 + (size_t)r * DD);
    uint4* d = reinterpret_cast<uint4*>(g_x16c + ((size_t)b * SS + slot) * DD);
    d[lane] = s[lane]; d[lane + 32] = s[lane + 32];
}

// merged QKV, single-pass fp16: grid=(4,128,3), 128 threads.
__global__ void __launch_bounds__(128, 2)
qkv_mm(int dummy) {
    extern __shared__ char smem[];
    const int z = blockIdx.z;
    int m0, b = 0;
    const __half* A;
    if (z == 0) {
        m0 = blockIdx.y * 128;
        A = g_x16;
    } else {
        b = blockIdx.y >> 4;
        m0 = (blockIdx.y & 15) * 128;
        if (m0 >= g_npad[b]) return;
        A = g_x16c + (size_t)b * SS * DD;
    }
    const int n0 = blockIdx.x * 128;

    float acc[4][8][4];
    gemm_1p(A, g_w16 + (size_t)z * DD * DD, DD, DD, DD, m0, n0, smem, acc);

    const int lane = threadIdx.x & 31;
    const int w = threadIdx.x >> 5;
    const int wm = w & 1, wn = w >> 1;
    const int mb = m0 + wm * 64 + (lane >> 2);
    const int nb = n0 + wn * 64 + (lane & 3) * 2;

    if (z == 0) {
#pragma unroll
        for (int mi = 0; mi < 4; mi++) {
            int m = mb + mi * 16;
#pragma unroll
            for (int nj = 0; nj < 8; nj++) {
                int n = nb + nj * 8;
                *reinterpret_cast<uint32_t*>(g_q16 + (size_t)m * DD + n) =
                    pack_h2(acc[mi][nj][0], acc[mi][nj][1]);
                *reinterpret_cast<uint32_t*>(g_q16 + (size_t)(m + 8) * DD + n) =
                    pack_h2(acc[mi][nj][2], acc[mi][nj][3]);
            }
        }
    } else if (z == 1) {
        __half* kk = g_k16 + (size_t)b * SS * DD;
#pragma unroll
        for (int mi = 0; mi < 4; mi++) {
            int m = mb + mi * 16;
#pragma unroll
            for (int nj = 0; nj < 8; nj++) {
                int n = nb + nj * 8;
                *reinterpret_cast<uint32_t*>(kk + (size_t)m * DD + n) =
                    pack_h2(acc[mi][nj][0], acc[mi][nj][1]);
                *reinterpret_cast<uint32_t*>(kk + (size_t)(m + 8) * DD + n) =
                    pack_h2(acc[mi][nj][2], acc[mi][nj][3]);
            }
        }
    } else {
        __half* vt = g_vt16 + (size_t)b * DD * SS;
#pragma unroll
        for (int mi = 0; mi < 4; mi++) {
#pragma unroll
            for (int half = 0; half < 2; half++) {
                int s = mb + mi * 16 + half * 8;
#pragma unroll
                for (int nj = 0; nj < 8; nj++) {
                    int d = nb + nj * 8;
                    vt[(size_t)d * SS + s]       = __float2half(acc[mi][nj][half * 2]);
                    vt[(size_t)(d + 1) * SS + s] = __float2half(acc[mi][nj][half * 2 + 1]);
                }
            }
        }
    }
}

// scores: single-pass fp16, fp16 logits. grid=(16,16,8), 128 threads
__global__ void __launch_bounds__(128, 2)
scores_mm(int dummy) {
    extern __shared__ char smem[];
    const int b = blockIdx.z;
    const int npad = g_npad[b];
    if (blockIdx.x * 128 >= npad) return;
    const int nv = g_nvalid[b];
    const int m0 = blockIdx.y * 128, n0 = blockIdx.x * 128;

    float acc[4][8][4];
    gemm_1p(g_q16 + (size_t)b * SS * DD, g_k16 + (size_t)b * SS * DD,
            DD, DD, DD, m0, n0, smem, acc);

    const int lane = threadIdx.x & 31;
    const int w = threadIdx.x >> 5;
    const int wm = w & 1, wn = w >> 1;
    const int mb = m0 + wm * 64 + (lane >> 2);
    const int nb = n0 + wn * 64 + (lane & 3) * 2;
    const float inv_scale = 0.0220970869120796101f;  // 1/sqrt(2048)
    __half* Pb = g_p16 + (size_t)b * SS * SS;

#pragma unroll
    for (int nj = 0; nj < 8; nj++) {
        int n = nb + nj * 8;
#pragma unroll
        for (int mi = 0; mi < 4; mi++) {
            int m = mb + mi * 16;
            float r0 = (n     < nv) ? acc[mi][nj][0] * inv_scale : -65504.0f;
            float r1 = (n + 1 < nv) ? acc[mi][nj][1] * inv_scale : -65504.0f;
            float r2 = (n     < nv) ? acc[mi][nj][2] * inv_scale : -65504.0f;
            float r3 = (n + 1 < nv) ? acc[mi][nj][3] * inv_scale : -65504.0f;
            *reinterpret_cast<uint32_t*>(Pb + (size_t)m * SS + n)       = pack_h2(r0, r1);
            *reinterpret_cast<uint32_t*>(Pb + (size_t)(m + 8) * SS + n) = pack_h2(r2, r3);
        }
    }
}

// softmax in place over fp16 logits. one block per (b,row)
__global__ void __launch_bounds__(256)
softmax_kernel() {
    __shared__ float red[8];
    const int b = blockIdx.x >> 11;
    const int W = g_npad[b];
    const size_t base = (size_t)blockIdx.x * SS;
    __half* p = g_p16 + base;
    const int tid = threadIdx.x;

    float v[8];
    const int x0 = tid * 8;
    bool active = (x0 < W);
    float mx = -1e30f;
    if (active) {
        uint4 u = *reinterpret_cast<const uint4*>(p + x0);
        const __half* hp = reinterpret_cast<const __half*>(&u);
#pragma unroll
        for (int i = 0; i < 8; i++) {
            v[i] = __half2float(hp[i]);
            mx = fmaxf(mx, v[i]);
        }
    }
#pragma unroll
    for (int o = 16; o > 0; o >>= 1) mx = fmaxf(mx, __shfl_xor_sync(0xffffffffu, mx, o));
    if ((tid & 31) == 0) red[tid >> 5] = mx;
    __syncthreads();
    mx = red[0];
#pragma unroll
    for (int wi = 1; wi < 8; wi++) mx = fmaxf(mx, red[wi]);

    float sum = 0.0f;
    if (active) {
#pragma unroll
        for (int i = 0; i < 8; i++) {
            v[i] = __expf(v[i] - mx);
            sum += v[i];
        }
    }
#pragma unroll
    for (int o = 16; o > 0; o >>= 1) sum += __shfl_xor_sync(0xffffffffu, sum, o);
    __syncthreads();
    if ((tid & 31) == 0) red[tid >> 5] = sum;
    __syncthreads();
    sum = 0.0f;
#pragma unroll
    for (int wi = 0; wi < 8; wi++) sum += red[wi];

    if (active) {
        const float rinv = 1.0f / sum;
        uint4 o;
        uint32_t* ow = reinterpret_cast<uint32_t*>(&o);
#pragma unroll
        for (int i = 0; i < 4; i++)
            ow[i] = pack_h2(v[2 * i] * rinv, v[2 * i + 1] * rinv);
        *reinterpret_cast<uint4*>(p + x0) = o;
    }
}

// PV single-pass fp16 over compacted K-dim: grid=(4,16,8), 128 threads
__global__ void __launch_bounds__(128, 2)
pv_mm(float* __restrict__ out) {
    extern __shared__ char smem[];
    const int b = blockIdx.z;
    const int W = g_npad[b];
    const int m0 = blockIdx.y * 128, n0 = blockIdx.x * 128;
    float acc[4][8][4];
    gemm_1p(g_p16 + (size_t)b * SS * SS, g_vt16 + (size_t)b * DD * SS,
            W, SS, SS, m0, n0, smem, acc);

    const int lane = threadIdx.x & 31;
    const int w = threadIdx.x >> 5;
    const int wm = w & 1, wn = w >> 1;
    const int mb = m0 + wm * 64 + (lane >> 2);
    const int nb = n0 + wn * 64 + (lane & 3) * 2;
    float* C = out + (size_t)b * SS * DD;
#pragma unroll
    for (int mi = 0; mi < 4; mi++) {
        int m = mb + mi * 16;
#pragma unroll
        for (int nj = 0; nj < 8; nj++) {
            int n = nb + nj * 8;
            *reinterpret_cast<float2*>(C + (size_t)m * DD + n) =
                make_float2(acc[mi][nj][0], acc[mi][nj][1]);
            *reinterpret_cast<float2*>(C + (size_t)(m + 8) * DD + n) =
                make_float2(acc[mi][nj][2], acc[mi][nj][3]);
        }
    }
}

// ---------------------------------------------------------------------------
extern "C" void kernel_launch(void* const* d_in, const int* in_sizes, int n_in,
                              void* d_out, int out_size) {
    const float* X    = (const float*)d_in[0];
    const int*   mask = (const int*)  d_in[1];
    const float* Wq   = (const float*)d_in[2];
    const float* Wk   = (const float*)d_in[3];
    const float* Wv   = (const float*)d_in[4];
    float* out = (float*)d_out;

    static bool attr_done = false;
    if (!attr_done) {
        cudaFuncSetAttribute(qkv_mm,    cudaFuncAttributeMaxDynamicSharedMemorySize, SMEM_BYTES);
        cudaFuncSetAttribute(scores_mm, cudaFuncAttributeMaxDynamicSharedMemorySize, SMEM_BYTES);
        cudaFuncSetAttribute(pv_mm,     cudaFuncAttributeMaxDynamicSharedMemorySize, SMEM_BYTES);
        attr_done = true;
    }

    const int nconv = NX4 + 3 * NW4;
    convert_all<<<(nconv + 255) / 256, 256>>>(X, Wq, Wk, Wv);
    build_index<<<BB, 256>>>(mask);
    gather_x<<<BB * SS / 8, 256>>>();

    dim3 blk(128);
    qkv_mm<<<dim3(DD / 128, 128, 3), blk, SMEM_BYTES>>>(0);
    scores_mm<<<dim3(SS / 128, SS / 128, BB), blk, SMEM_BYTES>>>(0);
    softmax_kernel<<<BB * SS, 256>>>();
    pv_mm<<<dim3(DD / 128, SS / 128, BB), blk, SMEM_BYTES>>>(out);
}

// round 17
// speedup vs baseline: 1.2140x; 1.2140x over previous
#include <cuda_runtime.h>
#include <cuda_fp16.h>
#include <cstdint>

#define BB 8
#define SS 2048
#define DD 512

// ---------------- device-global scratch (allocation-free) -------------------
__device__ __align__(16) __half g_x16 [(size_t)BB * SS * DD];  // X plain fp16
__device__ __align__(16) __half g_x16c[(size_t)BB * SS * DD];  // compacted X
__device__ __align__(16) __half g_w16 [3 * DD * DD];           // W plain fp16
__device__ __align__(16) __half g_q16 [(size_t)BB * SS * DD];  // Q plain fp16 (unscaled)
__device__ __align__(16) __half g_k16 [(size_t)BB * SS * DD];  // K plain fp16, compacted
__device__ __align__(16) __half g_vt16[(size_t)BB * DD * SS];  // V^T plain fp16 [b][d][slot]
__device__ __align__(16) __half g_p16 [(size_t)BB * SS * SS];  // logits -> probs (in place)
__device__ int g_slot[BB * SS];
__device__ int g_nvalid[BB];
__device__ int g_npad[BB];

// ---------------- PTX helpers ----------------------------------------------
static __device__ __forceinline__ uint32_t su32(const void* p) {
    return (uint32_t)__cvta_generic_to_shared(p);
}
__device__ __forceinline__ void cp16(uint32_t dst, const void* src) {
    asm volatile("cp.async.cg.shared.global [%0], [%1], 16;" :: "r"(dst), "l"(src));
}
__device__ __forceinline__ void cp_commit() {
    asm volatile("cp.async.commit_group;" ::: "memory");
}
template <int N>
__device__ __forceinline__ void cp_wait() {
    asm volatile("cp.async.wait_group %0;" :: "n"(N) : "memory");
}
__device__ __forceinline__ void ldm_x4(uint32_t addr, uint32_t r[4]) {
    asm volatile("ldmatrix.sync.aligned.m8n8.x4.shared.b16 {%0,%1,%2,%3}, [%4];"
                 : "=r"(r[0]), "=r"(r[1]), "=r"(r[2]), "=r"(r[3]) : "r"(addr));
}
__device__ __forceinline__ void mma_f16(float c[4], const uint32_t a[4], const uint32_t b[2]) {
    asm volatile(
        "mma.sync.aligned.m16n8k16.row.col.f32.f16.f16.f32 "
        "{%0,%1,%2,%3}, {%4,%5,%6,%7}, {%8,%9}, {%0,%1,%2,%3};"
        : "+f"(c[0]), "+f"(c[1]), "+f"(c[2]), "+f"(c[3])
        : "r"(a[0]), "r"(a[1]), "r"(a[2]), "r"(a[3]), "r"(b[0]), "r"(b[1]));
}
__device__ __forceinline__ uint32_t pack_h2(float a, float b) {
    __half2 t(__float2half(a), __float2half(b));
    return *reinterpret_cast<uint32_t*>(&t);
}

// ---------------- single-pass fp16 GEMM, CTA 128x128, warp 32x64, K-chunk 32 --
// 256 threads = 8 warps in 4(m) x 2(n). Stage = A(128x32)+B(128x32) at 80B pitch.
#define PITCH 80
#define TILE_B 10240           // 128 * 80
#define STAGE_B 20480          // 2 * TILE_B
#define NSTG 4
#define SMEM_BYTES (NSTG * STAGE_B)   // 81920

__device__ __forceinline__ void gemm_1p(const __half* __restrict__ Ag,
                                        const __half* __restrict__ Bg,
                                        int K, int ldA, int ldB,
                                        int m0, int n0,
                                        char* smem, float acc[2][8][4]) {
    const int tid  = threadIdx.x;
    const int lane = tid & 31;
    const int w    = tid >> 5;
    const int wm   = w & 3;
    const int wn   = w >> 2;
    const uint32_t sbase = su32(smem);

#pragma unroll
    for (int mi = 0; mi < 2; mi++)
#pragma unroll
        for (int nj = 0; nj < 8; nj++)
#pragma unroll
            for (int e = 0; e < 4; e++) acc[mi][nj][e] = 0.0f;

    const int NK = K >> 5;
    const int r0 = tid >> 1;             // row 0..127
    const int cB = (tid & 1) * 32;       // byte col 0 / 32 (each thread: 2x16B)
    const int cH = (tid & 1) * 16;       // half col

    const uint32_t offA = (uint32_t)(wm * 32 + (lane & 15)) * PITCH + (lane >> 4) * 16;
    const uint32_t offB = (uint32_t)(wn * 64 + (lane & 7) + ((lane >> 4) << 3)) * PITCH
                        + (((lane >> 3) & 1) << 4);

#define ISSUE1(kidx)                                                              \
    do {                                                                          \
        const int k0 = (kidx) << 5;                                               \
        uint32_t st = sbase + ((kidx) & (NSTG - 1)) * STAGE_B;                    \
        size_t ga = (size_t)(m0 + r0) * ldA + k0 + cH;                            \
        size_t gb = (size_t)(n0 + r0) * ldB + k0 + cH;                            \
        uint32_t da = st + r0 * PITCH + cB;                                       \
        cp16(da,               Ag + ga);                                          \
        cp16(da + 16,          Ag + ga + 8);                                      \
        cp16(da + TILE_B,      Bg + gb);                                          \
        cp16(da + TILE_B + 16, Bg + gb + 8);                                      \
        cp_commit();                                                              \
    } while (0)

    ISSUE1(0); ISSUE1(1); ISSUE1(2);

    for (int k = 0; k < NK; k++) {
        cp_wait<2>();
        __syncthreads();

        const uint32_t st = sbase + (k & (NSTG - 1)) * STAGE_B;
#pragma unroll
        for (int kk2 = 0; kk2 < 2; kk2++) {
            const uint32_t ko = kk2 * 32;   // 16 halves = 32 bytes
            uint32_t ah[2][4];
#pragma unroll
            for (int mi = 0; mi < 2; mi++)
                ldm_x4(st + offA + ko + (uint32_t)(mi * 16 * PITCH), ah[mi]);
            uint32_t bh[8][2];
#pragma unroll
            for (int nj4 = 0; nj4 < 4; nj4++) {
                uint32_t t[4];
                ldm_x4(st + TILE_B + offB + ko + (uint32_t)(nj4 * 16 * PITCH), t);
                bh[2 * nj4][0] = t[0]; bh[2 * nj4][1] = t[1];
                bh[2 * nj4 + 1][0] = t[2]; bh[2 * nj4 + 1][1] = t[3];
            }
#pragma unroll
            for (int mi = 0; mi < 2; mi++)
#pragma unroll
                for (int nj = 0; nj < 8; nj++)
                    mma_f16(acc[mi][nj], ah[mi], bh[nj]);
        }

        if (k + 3 < NK) ISSUE1(k + 3);
        else            cp_commit();
    }
#undef ISSUE1
}

// ---------------- kernels ----------------------------------------------------
#define NX4 ((BB * SS * DD) / 4)
#define NW4 ((DD * DD) / 4)
// convert X + W to fp16; also scatter compacted X rows (g_slot must be built)
__global__ void __launch_bounds__(256)
convert_all(const float* __restrict__ X, const float* __restrict__ Wq,
            const float* __restrict__ Wk, const float* __restrict__ Wv) {
    int i = blockIdx.x * blockDim.x + threadIdx.x;
    if (i < NX4) {
        float4 v = reinterpret_cast<const float4*>(X)[i];
        uint2 hv = make_uint2(pack_h2(v.x, v.y), pack_h2(v.z, v.w));
        reinterpret_cast<uint2*>(g_x16)[i] = hv;
        const int r = i >> 7;                 // row (DD/4 = 128 uint2 per row)
        const int slot = g_slot[r];
        if (slot >= 0) {
            const int b = r >> 11;
            const int c = i & 127;
            reinterpret_cast<uint2*>(g_x16c)[(((size_t)b * SS + slot) * DD >> 2) + c] = hv;
        }
        return;
    }
    int i2 = i - NX4;
    int wsel = i2 / NW4;
    if (wsel >= 3) return;
    int j = i2 - wsel * NW4;
    const float* src = (wsel == 0) ? Wq : ((wsel == 1) ? Wk : Wv);
    float4 v = reinterpret_cast<const float4*>(src)[j];
    reinterpret_cast<uint2*>(g_w16 + (size_t)wsel * DD * DD)[j] =
        make_uint2(pack_h2(v.x, v.y), pack_h2(v.z, v.w));
}

__global__ void __launch_bounds__(256)
build_index(const int* __restrict__ mask) {
    const int b = blockIdx.x;
    const int t = threadIdx.x;
    const int* m = mask + b * SS;
    const int base = t * 8;
    int loc[8], cnt = 0;
#pragma unroll
    for (int i = 0; i < 8; i++) { loc[i] = (m[base + i] != 0); cnt += loc[i]; }
    const int lane = t & 31, w = t >> 5;
    int v = cnt;
#pragma unroll
    for (int o = 1; o < 32; o <<= 1) {
        int u = __shfl_up_sync(0xffffffffu, v, o);
        if (lane >= o) v += u;
    }
    __shared__ int ws[8];
    if (lane == 31) ws[w] = v;
    __syncthreads();
    int wo = 0;
#pragma unroll
    for (int i = 0; i < 8; i++) if (i < w) wo += ws[i];
    int excl = wo + v - cnt;
#pragma unroll
    for (int i = 0; i < 8; i++) {
        g_slot[b * SS + base + i] = loc[i] ? excl : -1;
        excl += loc[i];
    }
    if (t == 255) {
        int tot = wo + v;
        g_nvalid[b] = tot;
        g_npad[b]   = (tot + 127) & ~127;
    }
}

// merged QKV, single-pass fp16: grid=(4,128,3), 256 threads.
__global__ void __launch_bounds__(256, 2)
qkv_mm(int dummy) {
    extern __shared__ char smem[];
    const int z = blockIdx.z;
    int m0, b = 0;
    const __half* A;
    if (z == 0) {
        m0 = blockIdx.y * 128;
        A = g_x16;
    } else {
        b = blockIdx.y >> 4;
        m0 = (blockIdx.y & 15) * 128;
        if (m0 >= g_npad[b]) return;
        A = g_x16c + (size_t)b * SS * DD;
    }
    const int n0 = blockIdx.x * 128;

    float acc[2][8][4];
    gemm_1p(A, g_w16 + (size_t)z * DD * DD, DD, DD, DD, m0, n0, smem, acc);

    const int lane = threadIdx.x & 31;
    const int w = threadIdx.x >> 5;
    const int wm = w & 3, wn = w >> 2;
    const int mb = m0 + wm * 32 + (lane >> 2);
    const int nb = n0 + wn * 64 + (lane & 3) * 2;

    if (z == 0) {
#pragma unroll
        for (int mi = 0; mi < 2; mi++) {
            int m = mb + mi * 16;
#pragma unroll
            for (int nj = 0; nj < 8; nj++) {
                int n = nb + nj * 8;
                *reinterpret_cast<uint32_t*>(g_q16 + (size_t)m * DD + n) =
                    pack_h2(acc[mi][nj][0], acc[mi][nj][1]);
                *reinterpret_cast<uint32_t*>(g_q16 + (size_t)(m + 8) * DD + n) =
                    pack_h2(acc[mi][nj][2], acc[mi][nj][3]);
            }
        }
    } else if (z == 1) {
        __half* kk = g_k16 + (size_t)b * SS * DD;
#pragma unroll
        for (int mi = 0; mi < 2; mi++) {
            int m = mb + mi * 16;
#pragma unroll
            for (int nj = 0; nj < 8; nj++) {
                int n = nb + nj * 8;
                *reinterpret_cast<uint32_t*>(kk + (size_t)m * DD + n) =
                    pack_h2(acc[mi][nj][0], acc[mi][nj][1]);
                *reinterpret_cast<uint32_t*>(kk + (size_t)(m + 8) * DD + n) =
                    pack_h2(acc[mi][nj][2], acc[mi][nj][3]);
            }
        }
    } else {
        __half* vt = g_vt16 + (size_t)b * DD * SS;
#pragma unroll
        for (int mi = 0; mi < 2; mi++) {
#pragma unroll
            for (int half = 0; half < 2; half++) {
                int s = mb + mi * 16 + half * 8;
#pragma unroll
                for (int nj = 0; nj < 8; nj++) {
                    int d = nb + nj * 8;
                    vt[(size_t)d * SS + s]       = __float2half(acc[mi][nj][half * 2]);
                    vt[(size_t)(d + 1) * SS + s] = __float2half(acc[mi][nj][half * 2 + 1]);
                }
            }
        }
    }
}

// scores: single-pass fp16, fp16 logits. grid=(16,16,8)
__global__ void __launch_bounds__(256, 2)
scores_mm(int dummy) {
    extern __shared__ char smem[];
    const int b = blockIdx.z;
    const int npad = g_npad[b];
    if (blockIdx.x * 128 >= npad) return;
    const int nv = g_nvalid[b];
    const int m0 = blockIdx.y * 128, n0 = blockIdx.x * 128;

    float acc[2][8][4];
    gemm_1p(g_q16 + (size_t)b * SS * DD, g_k16 + (size_t)b * SS * DD,
            DD, DD, DD, m0, n0, smem, acc);

    const int lane = threadIdx.x & 31;
    const int w = threadIdx.x >> 5;
    const int wm = w & 3, wn = w >> 2;
    const int mb = m0 + wm * 32 + (lane >> 2);
    const int nb = n0 + wn * 64 + (lane & 3) * 2;
    const float inv_scale = 0.0220970869120796101f;  // 1/sqrt(2048)
    __half* Pb = g_p16 + (size_t)b * SS * SS;

#pragma unroll
    for (int nj = 0; nj < 8; nj++) {
        int n = nb + nj * 8;
#pragma unroll
        for (int mi = 0; mi < 2; mi++) {
            int m = mb + mi * 16;
            float r0 = (n     < nv) ? acc[mi][nj][0] * inv_scale : -65504.0f;
            float r1 = (n + 1 < nv) ? acc[mi][nj][1] * inv_scale : -65504.0f;
            float r2 = (n     < nv) ? acc[mi][nj][2] * inv_scale : -65504.0f;
            float r3 = (n + 1 < nv) ? acc[mi][nj][3] * inv_scale : -65504.0f;
            *reinterpret_cast<uint32_t*>(Pb + (size_t)m * SS + n)       = pack_h2(r0, r1);
            *reinterpret_cast<uint32_t*>(Pb + (size_t)(m + 8) * SS + n) = pack_h2(r2, r3);
        }
    }
}

// softmax in place over fp16 logits. one block per (b,row)
__global__ void __launch_bounds__(256)
softmax_kernel() {
    __shared__ float red[8];
    const int b = blockIdx.x >> 11;
    const int W = g_npad[b];
    const size_t base = (size_t)blockIdx.x * SS;
    __half* p = g_p16 + base;
    const int tid = threadIdx.x;

    float v[8];
    const int x0 = tid * 8;
    bool active = (x0 < W);
    float mx = -1e30f;
    if (active) {
        uint4 u = *reinterpret_cast<const uint4*>(p + x0);
        const __half* hp = reinterpret_cast<const __half*>(&u);
#pragma unroll
        for (int i = 0; i < 8; i++) {
            v[i] = __half2float(hp[i]);
            mx = fmaxf(mx, v[i]);
        }
    }
#pragma unroll
    for (int o = 16; o > 0; o >>= 1) mx = fmaxf(mx, __shfl_xor_sync(0xffffffffu, mx, o));
    if ((tid & 31) == 0) red[tid >> 5] = mx;
    __syncthreads();
    mx = red[0];
#pragma unroll
    for (int wi = 1; wi < 8; wi++) mx = fmaxf(mx, red[wi]);

    float sum = 0.0f;
    if (active) {
#pragma unroll
        for (int i = 0; i < 8; i++) {
            v[i] = __expf(v[i] - mx);
            sum += v[i];
        }
    }
#pragma unroll
    for (int o = 16; o > 0; o >>= 1) sum += __shfl_xor_sync(0xffffffffu, sum, o);
    __syncthreads();
    if ((tid & 31) == 0) red[tid >> 5] = sum;
    __syncthreads();
    sum = 0.0f;
#pragma unroll
    for (int wi = 0; wi < 8; wi++) sum += red[wi];

    if (active) {
        const float rinv = 1.0f / sum;
        uint4 o;
        uint32_t* ow = reinterpret_cast<uint32_t*>(&o);
#pragma unroll
        for (int i = 0; i < 4; i++)
            ow[i] = pack_h2(v[2 * i] * rinv, v[2 * i + 1] * rinv);
        *reinterpret_cast<uint4*>(p + x0) = o;
    }
}

// PV single-pass fp16 over compacted K-dim: grid=(4,16,8)
__global__ void __launch_bounds__(256, 2)
pv_mm(float* __restrict__ out) {
    extern __shared__ char smem[];
    const int b = blockIdx.z;
    const int W = g_npad[b];
    const int m0 = blockIdx.y * 128, n0 = blockIdx.x * 128;
    float acc[2][8][4];
    gemm_1p(g_p16 + (size_t)b * SS * SS, g_vt16 + (size_t)b * DD * SS,
            W, SS, SS, m0, n0, smem, acc);

    const int lane = threadIdx.x & 31;
    const int w = threadIdx.x >> 5;
    const int wm = w & 3, wn = w >> 2;
    const int mb = m0 + wm * 32 + (lane >> 2);
    const int nb = n0 + wn * 64 + (lane & 3) * 2;
    float* C = out + (size_t)b * SS * DD;
#pragma unroll
    for (int mi = 0; mi < 2; mi++) {
        int m = mb + mi * 16;
#pragma unroll
        for (int nj = 0; nj < 8; nj++) {
            int n = nb + nj * 8;
            *reinterpret_cast<float2*>(C + (size_t)m * DD + n) =
                make_float2(acc[mi][nj][0], acc[mi][nj][1]);
            *reinterpret_cast<float2*>(C + (size_t)(m + 8) * DD + n) =
                make_float2(acc[mi][nj][2], acc[mi][nj][3]);
        }
    }
}

// ---------------------------------------------------------------------------
extern "C" void kernel_launch(void* const* d_in, const int* in_sizes, int n_in,
                              void* d_out, int out_size) {
    const float* X    = (const float*)d_in[0];
    const int*   mask = (const int*)  d_in[1];
    const float* Wq   = (const float*)d_in[2];
    const float* Wk   = (const float*)d_in[3];
    const float* Wv   = (const float*)d_in[4];
    float* out = (float*)d_out;

    static bool attr_done = false;
    if (!attr_done) {
        cudaFuncSetAttribute(qkv_mm,    cudaFuncAttributeMaxDynamicSharedMemorySize, SMEM_BYTES);
        cudaFuncSetAttribute(scores_mm, cudaFuncAttributeMaxDynamicSharedMemorySize, SMEM_BYTES);
        cudaFuncSetAttribute(pv_mm,     cudaFuncAttributeMaxDynamicSharedMemorySize, SMEM_BYTES);
        attr_done = true;
    }

    build_index<<<BB, 256>>>(mask);
    const int nconv = NX4 + 3 * NW4;
    convert_all<<<(nconv + 255) / 256, 256>>>(X, Wq, Wk, Wv);

    dim3 blk(256);
    qkv_mm<<<dim3(DD / 128, 128, 3), blk, SMEM_BYTES>>>(0);
    scores_mm<<<dim3(SS / 128, SS / 128, BB), blk, SMEM_BYTES>>>(0);
    softmax_kernel<<<BB * SS, 256>>>();
    pv_mm<<<dim3(DD / 128, SS / 128, BB), blk, SMEM_BYTES>>>(out);
}